// round 7
// baseline (speedup 1.0000x reference)
#include <cuda_runtime.h>
#include <cstdint>
#include <cstddef>

#define BB 4
#define NN 8192
#define SS 2048
#define KK 32
#define DD 64

// group indices scratch: [B*S, K]
__device__ int g_grp[BB * SS * KK];

// ------------------------------------------------------------------
// Kernel 1: farthest point sampling. One block per batch.
// 1024 threads, 8 points/thread in registers. Bit-exact replication of
//   d = ((x-cx)^2 + (y-cy)^2) + (z-cz)^2 ; dists = min(dists, d);
//   nxt = argmax(dists)  (first-index tie-break)
// Pure fp32 mul/add (verified bit-exact vs XLA in R4-R6).
// ------------------------------------------------------------------
__global__ __launch_bounds__(1024, 1)
void fps_kernel(const float* __restrict__ xyz, float* __restrict__ newxyz)
{
    extern __shared__ float4 sxyz[];           // 8192 * 16B = 128KB
    __shared__ unsigned long long wkey[32];
    __shared__ unsigned long long skey;

    const int b   = blockIdx.x;
    const int tid = threadIdx.x;
    const float* xb = xyz + (size_t)b * NN * 3;

    float px[8], py[8], pz[8], dist[8];
#pragma unroll
    for (int j = 0; j < 8; j++) {
        int p = tid * 8 + j;
        float x = xb[p * 3 + 0];
        float y = xb[p * 3 + 1];
        float z = xb[p * 3 + 2];
        px[j] = x; py[j] = y; pz[j] = z;
        dist[j] = 1e10f;
        sxyz[p] = make_float4(x, y, z, 0.0f);
    }
    __syncthreads();

    int cur = 0;
    for (int s = 0; s < SS; s++) {
        float4 c4 = sxyz[cur];                 // LDS.128 broadcast
        if (tid == 0) {
            float* o = newxyz + ((size_t)b * SS + s) * 3;
            o[0] = c4.x; o[1] = c4.y; o[2] = c4.z;
        }
        float bv = -1.0f;
        int   bi = 0;
#pragma unroll
        for (int j = 0; j < 8; j++) {
            float dx = __fsub_rn(px[j], c4.x);
            float dy = __fsub_rn(py[j], c4.y);
            float dz = __fsub_rn(pz[j], c4.z);
            float d  = __fadd_rn(__fadd_rn(__fmul_rn(dx, dx), __fmul_rn(dy, dy)),
                                 __fmul_rn(dz, dz));
            float nd = fminf(dist[j], d);
            dist[j] = nd;
            if (nd > bv) { bv = nd; bi = tid * 8 + j; }
        }
        // high 32 bits = dist (>=0 so uint order == float order),
        // low 32 = ~index so max picks SMALLEST index among ties.
        unsigned long long key =
            ((unsigned long long)__float_as_uint(bv) << 32) |
            (unsigned int)(~(unsigned int)bi);
#pragma unroll
        for (int off = 16; off; off >>= 1) {
            unsigned long long ok = __shfl_xor_sync(0xffffffffu, key, off);
            if (ok > key) key = ok;
        }
        if ((tid & 31) == 0) wkey[tid >> 5] = key;
        __syncthreads();
        if (tid < 32) {
            unsigned long long k2 = wkey[tid];
#pragma unroll
            for (int off = 16; off; off >>= 1) {
                unsigned long long ok = __shfl_xor_sync(0xffffffffu, k2, off);
                if (ok > k2) k2 = ok;
            }
            if (tid == 0) skey = k2;
        }
        __syncthreads();
        cur = (int)(~(unsigned int)(skey & 0xffffffffull));
    }
}

// ------------------------------------------------------------------
// Kernel 2: ball query. One warp per centroid.
// sq = (|c|^2 + |p|^2) - 2*(c.p).
// nsq/xsq: jnp.sum(x**2) -> rounded squares, left-assoc adds
//          (same elementwise pattern as FPS, verified no fma there).
// dot:     dot_general -> fp32 GEMM fma chain, k ascending,
//          acc0 = 0  =>  fmaf(nz,z, fmaf(ny,y, nx*x)).
// Exclusion when sq > 0.04f. First K hits ascending; pad with first.
// ------------------------------------------------------------------
__global__ __launch_bounds__(256)
void ballq_kernel(const float* __restrict__ xyz,
                  const float* __restrict__ newxyz)
{
    const int w    = (blockIdx.x * blockDim.x + threadIdx.x) >> 5;
    const int lane = threadIdx.x & 31;
    const int b = w >> 11;                      // w / 2048
    const float* xb = xyz + (size_t)b * NN * 3;
    const float* nw = newxyz + (size_t)w * 3;

    float nx = nw[0], ny = nw[1], nz = nw[2];
    float nsq = __fadd_rn(__fadd_rn(__fmul_rn(nx, nx), __fmul_rn(ny, ny)),
                          __fmul_rn(nz, nz));
    int cnt = 0;
    int first = 0;
    int* g = g_grp + (size_t)w * KK;

    for (int base = 0; base < NN; base += 32) {
        int p = base + lane;
        float x = xb[p * 3 + 0];
        float y = xb[p * 3 + 1];
        float z = xb[p * 3 + 2];
        float xsq = __fadd_rn(__fadd_rn(__fmul_rn(x, x), __fmul_rn(y, y)),
                              __fmul_rn(z, z));
        // fp32 GEMM-style fma chain (products unrounded except the first)
        float dot = __fmaf_rn(nz, z, __fmaf_rn(ny, y, __fmul_rn(nx, x)));
        float sq  = __fsub_rn(__fadd_rn(nsq, xsq), __fmul_rn(2.0f, dot));
        bool hit  = !(sq > 0.04f);
        unsigned m = __ballot_sync(0xffffffffu, hit);
        if (cnt == 0 && m) first = base + __ffs(m) - 1;
        int pos = cnt + __popc(m & ((1u << lane) - 1u));
        if (hit && pos < KK) g[pos] = p;
        cnt += __popc(m);
        if (cnt >= KK) break;
    }
    if (cnt < KK) {
        for (int k = cnt + lane; k < KK; k += 32) g[k] = first;
    }
}

// ------------------------------------------------------------------
// Kernel 3: gather + 3-layer pointwise MLP + max-pool over K.
// Warp = one group, lane = one neighbor. Pure fp32 fma chains
// (reference MLP is fp32 per R4/R6 quadrature analysis).
// Shared float layout:
//   sW1 [0, 4352)      64 rows x 68 (row-padded, pad=0)
//   sW2 [4352, 12544)  128 x 64
//   sW3 [12544, 45312) 256 x 128
//   sb1 [45312,45376)  sb2 [45376,45504)  sb3 [45504,45760)
// total 45760 floats = 183040 bytes.
// ------------------------------------------------------------------
#define OFF_W1 0
#define OFF_W2 4352
#define OFF_W3 12544
#define OFF_B1 45312
#define OFF_B2 45376
#define OFF_B3 45504
#define SMEM_FLOATS 45760

__global__ __launch_bounds__(256, 1)
void mlp_kernel(const float* __restrict__ xyz,
                const float* __restrict__ features,
                const float* __restrict__ W1, const float* __restrict__ b1,
                const float* __restrict__ W2, const float* __restrict__ b2,
                const float* __restrict__ W3, const float* __restrict__ b3,
                const float* __restrict__ newxyz,
                float* __restrict__ feats_out)
{
    extern __shared__ float sm[];
    const int tid  = threadIdx.x;
    const int lane = tid & 31;

    // ---- stage weights + biases ----
    for (int t = tid; t < 64 * 68; t += 256) {
        int o = t / 68, i = t - o * 68;
        sm[OFF_W1 + t] = (i < 67) ? W1[o * 67 + i] : 0.0f;
    }
    for (int t = tid; t < 128 * 64; t += 256) sm[OFF_W2 + t] = W2[t];
    for (int t = tid; t < 256 * 128; t += 256) sm[OFF_W3 + t] = W3[t];
    if (tid < 64)  sm[OFF_B1 + tid] = b1[tid];
    if (tid < 128) sm[OFF_B2 + tid] = b2[tid];
    sm[OFF_B3 + tid] = b3[tid & 255];
    __syncthreads();

    const int g = blockIdx.x * 8 + (tid >> 5);   // group id, 8192 total
    const int b = g >> 11;                       // g / 2048
    const int gi = g_grp[(size_t)g * KK + lane];

    // ---- h0 = [xyz - center (3), features (64), pad (1)] ----
    float h0[68];
    {
        const float* ctr  = newxyz + (size_t)g * 3;
        const float* pxyz = xyz + ((size_t)b * NN + gi) * 3;
        h0[0] = pxyz[0] - ctr[0];
        h0[1] = pxyz[1] - ctr[1];
        h0[2] = pxyz[2] - ctr[2];
        const float* fr = features + ((size_t)b * NN + gi) * DD;
#pragma unroll
        for (int t = 0; t < 64; t++) h0[3 + t] = fr[t];
        h0[67] = 0.0f;
    }

    // ---- layer 1: 67 -> 64 ----
    float h1[64];
#pragma unroll
    for (int o = 0; o < 64; o++) {
        float acc = sm[OFF_B1 + o];
        const float4* wr = (const float4*)(sm + OFF_W1 + o * 68);
#pragma unroll
        for (int t = 0; t < 17; t++) {
            float4 wv = wr[t];
            acc = fmaf(wv.x, h0[4 * t + 0], acc);
            acc = fmaf(wv.y, h0[4 * t + 1], acc);
            acc = fmaf(wv.z, h0[4 * t + 2], acc);
            acc = fmaf(wv.w, h0[4 * t + 3], acc);
        }
        h1[o] = fmaxf(acc, 0.0f);
    }

    // ---- layer 2: 64 -> 128 ----
    float h2[128];
#pragma unroll
    for (int o = 0; o < 128; o++) {
        float acc = sm[OFF_B2 + o];
        const float4* wr = (const float4*)(sm + OFF_W2 + o * 64);
#pragma unroll
        for (int t = 0; t < 16; t++) {
            float4 wv = wr[t];
            acc = fmaf(wv.x, h1[4 * t + 0], acc);
            acc = fmaf(wv.y, h1[4 * t + 1], acc);
            acc = fmaf(wv.z, h1[4 * t + 2], acc);
            acc = fmaf(wv.w, h1[4 * t + 3], acc);
        }
        h2[o] = fmaxf(acc, 0.0f);
    }

    // ---- layer 3: 128 -> 256, streamed, fused max-pool over lanes ----
    float maxv[8];
#pragma unroll
    for (int c = 0; c < 8; c++) {
        for (int oo = 0; oo < 32; oo++) {     // dynamic loop (small code)
            int o = c * 32 + oo;
            float acc = sm[OFF_B3 + o];
            const float4* wr = (const float4*)(sm + OFF_W3 + o * 128);
#pragma unroll
            for (int t = 0; t < 32; t++) {
                float4 wv = wr[t];
                acc = fmaf(wv.x, h2[4 * t + 0], acc);
                acc = fmaf(wv.y, h2[4 * t + 1], acc);
                acc = fmaf(wv.z, h2[4 * t + 2], acc);
                acc = fmaf(wv.w, h2[4 * t + 3], acc);
            }
            acc = fmaxf(acc, 0.0f);
#pragma unroll
            for (int off = 16; off; off >>= 1)
                acc = fmaxf(acc, __shfl_xor_sync(0xffffffffu, acc, off));
            if (oo == lane) maxv[c] = acc;
        }
    }
#pragma unroll
    for (int c = 0; c < 8; c++)
        feats_out[(size_t)g * 256 + c * 32 + lane] = maxv[c];
}

// ------------------------------------------------------------------
extern "C" void kernel_launch(void* const* d_in, const int* in_sizes, int n_in,
                              void* d_out, int out_size)
{
    const float* xyz      = (const float*)d_in[0];
    const float* features = (const float*)d_in[1];
    const float* W1 = (const float*)d_in[2];
    const float* b1 = (const float*)d_in[3];
    const float* W2 = (const float*)d_in[4];
    const float* b2 = (const float*)d_in[5];
    const float* W3 = (const float*)d_in[6];
    const float* b3 = (const float*)d_in[7];

    float* out    = (float*)d_out;
    float* newxyz = out;                         // [B,S,3] = 24576 floats
    float* feats  = out + (size_t)BB * SS * 3;   // [B,S,256]

    cudaFuncSetAttribute(fps_kernel, cudaFuncAttributeMaxDynamicSharedMemorySize,
                         NN * (int)sizeof(float4));
    cudaFuncSetAttribute(mlp_kernel, cudaFuncAttributeMaxDynamicSharedMemorySize,
                         SMEM_FLOATS * (int)sizeof(float));

    fps_kernel<<<BB, 1024, NN * sizeof(float4)>>>(xyz, newxyz);
    ballq_kernel<<<(BB * SS * 32) / 256, 256>>>(xyz, newxyz);
    mlp_kernel<<<(BB * SS) / 8, 256, SMEM_FLOATS * sizeof(float)>>>(
        xyz, features, W1, b1, W2, b2, W3, b3, newxyz, feats);
}

// round 9
// speedup vs baseline: 1.5325x; 1.5325x over previous
#include <cuda_runtime.h>
#include <cstdint>
#include <cstddef>

#define BB 4
#define NN 8192
#define SS 2048
#define KK 32
#define DD 64

// group indices scratch: [B*S, K]
__device__ int g_grp[BB * SS * KK];

// ---------------- packed f32x2 helpers (per-lane IEEE == scalar) ----------
__device__ __forceinline__ unsigned long long pk2(float lo, float hi) {
    unsigned long long r;
    asm("mov.b64 %0, {%1, %2};" : "=l"(r) : "f"(lo), "f"(hi));
    return r;
}
__device__ __forceinline__ void upk2(unsigned long long v, float& lo, float& hi) {
    asm("mov.b64 {%0, %1}, %2;" : "=f"(lo), "=f"(hi) : "l"(v));
}
__device__ __forceinline__ unsigned long long add2(unsigned long long a, unsigned long long b) {
    unsigned long long r;
    asm("add.rn.f32x2 %0, %1, %2;" : "=l"(r) : "l"(a), "l"(b));
    return r;
}
__device__ __forceinline__ unsigned long long mul2(unsigned long long a, unsigned long long b) {
    unsigned long long r;
    asm("mul.rn.f32x2 %0, %1, %2;" : "=l"(r) : "l"(a), "l"(b));
    return r;
}
__device__ __forceinline__ void fma2(unsigned long long& d, unsigned long long a, unsigned long long b) {
    asm("fma.rn.f32x2 %0, %1, %2, %0;" : "+l"(d) : "l"(a), "l"(b));
}

// ------------------------------------------------------------------
// Kernel 1: farthest point sampling. One block per batch.
// 1024 threads, 8 points/thread. Distances computed pairwise with
// packed f32x2 (bitwise == scalar: sub == add of exact negation,
// rounded squares, left-assoc (x2+y2)+z2, min per point).
// Argmax: running fmaxf + post-loop first-index equality scan;
// warp/block reduce via redux.max on dist bits (lane order == index
// order -> ffs = first-index tie-break, matching jnp.argmax).
// One barrier per iteration (parity double-buffered stage).
// ------------------------------------------------------------------
__global__ __launch_bounds__(1024, 1)
void fps_kernel(const float* __restrict__ xyz, float* __restrict__ newxyz)
{
    extern __shared__ float4 sxyz[];           // 8192 * 16B = 128KB
    __shared__ unsigned int sd[2][32];
    __shared__ int          si[2][32];

    const int b    = blockIdx.x;
    const int tid  = threadIdx.x;
    const int lane = tid & 31;
    const float* xb = xyz + (size_t)b * NN * 3;

    unsigned long long pxp[4], pyp[4], pzp[4];
    float dist[8];
#pragma unroll
    for (int j = 0; j < 4; j++) {
        int p0 = tid * 8 + 2 * j;
        float x0 = xb[p0 * 3 + 0], y0 = xb[p0 * 3 + 1], z0 = xb[p0 * 3 + 2];
        float x1 = xb[p0 * 3 + 3], y1 = xb[p0 * 3 + 4], z1 = xb[p0 * 3 + 5];
        pxp[j] = pk2(x0, x1); pyp[j] = pk2(y0, y1); pzp[j] = pk2(z0, z1);
        dist[2 * j] = 1e10f; dist[2 * j + 1] = 1e10f;
        sxyz[p0]     = make_float4(x0, y0, z0, 0.0f);
        sxyz[p0 + 1] = make_float4(x1, y1, z1, 0.0f);
    }
    __syncthreads();

    int cur = 0;
    for (int s = 0; s < SS; s++) {
        float4 c4 = sxyz[cur];                 // LDS.128 broadcast
        if (tid == 0) {
            float* o = newxyz + ((size_t)b * SS + s) * 3;
            o[0] = c4.x; o[1] = c4.y; o[2] = c4.z;
        }
        unsigned long long cx2 = pk2(-c4.x, -c4.x);
        unsigned long long cy2 = pk2(-c4.y, -c4.y);
        unsigned long long cz2 = pk2(-c4.z, -c4.z);
        float bv = -1.0f;
#pragma unroll
        for (int j = 0; j < 4; j++) {
            unsigned long long dx = add2(pxp[j], cx2);
            unsigned long long dy = add2(pyp[j], cy2);
            unsigned long long dz = add2(pzp[j], cz2);
            unsigned long long dd = add2(add2(mul2(dx, dx), mul2(dy, dy)),
                                         mul2(dz, dz));
            float dl, dh; upk2(dd, dl, dh);
            float n0 = fminf(dist[2 * j],     dl);
            float n1 = fminf(dist[2 * j + 1], dh);
            dist[2 * j]     = n0;
            dist[2 * j + 1] = n1;
            bv = fmaxf(bv, fmaxf(n0, n1));
        }
        // first j with dist[j]==bv (bv exactly equals one of them)
        int bi = 0;
#pragma unroll
        for (int j = 7; j >= 0; j--) if (dist[j] == bv) bi = j;

        unsigned db = __float_as_uint(bv);     // dist>=0: uint order == float order
        unsigned wm = __reduce_max_sync(0xffffffffu, db);
        unsigned bl = __ballot_sync(0xffffffffu, db == wm);
        int src  = __ffs(bl) - 1;              // smallest lane == smallest index
        int widx = __shfl_sync(0xffffffffu, tid * 8 + bi, src);

        int par = s & 1;
        if (lane == 0) { sd[par][tid >> 5] = wm; si[par][tid >> 5] = widx; }
        __syncthreads();
        unsigned vd = sd[par][lane];
        int      vi = si[par][lane];
        unsigned m2 = __reduce_max_sync(0xffffffffu, vd);
        unsigned b2 = __ballot_sync(0xffffffffu, vd == m2);
        int s2 = __ffs(b2) - 1;                // smallest warp == smallest index
        cur = __shfl_sync(0xffffffffu, vi, s2);
    }
}

// ------------------------------------------------------------------
// Kernel 2: ball query. One warp per centroid. (unchanged; verified)
// ------------------------------------------------------------------
__global__ __launch_bounds__(256)
void ballq_kernel(const float* __restrict__ xyz,
                  const float* __restrict__ newxyz)
{
    const int w    = (blockIdx.x * blockDim.x + threadIdx.x) >> 5;
    const int lane = threadIdx.x & 31;
    const int b = w >> 11;                      // w / 2048
    const float* xb = xyz + (size_t)b * NN * 3;
    const float* nw = newxyz + (size_t)w * 3;

    float nx = nw[0], ny = nw[1], nz = nw[2];
    float nsq = __fadd_rn(__fadd_rn(__fmul_rn(nx, nx), __fmul_rn(ny, ny)),
                          __fmul_rn(nz, nz));
    int cnt = 0;
    int first = 0;
    int* g = g_grp + (size_t)w * KK;

    for (int base = 0; base < NN; base += 32) {
        int p = base + lane;
        float x = xb[p * 3 + 0];
        float y = xb[p * 3 + 1];
        float z = xb[p * 3 + 2];
        float xsq = __fadd_rn(__fadd_rn(__fmul_rn(x, x), __fmul_rn(y, y)),
                              __fmul_rn(z, z));
        float dot = __fmaf_rn(nz, z, __fmaf_rn(ny, y, __fmul_rn(nx, x)));
        float sq  = __fsub_rn(__fadd_rn(nsq, xsq), __fmul_rn(2.0f, dot));
        bool hit  = !(sq > 0.04f);
        unsigned m = __ballot_sync(0xffffffffu, hit);
        if (cnt == 0 && m) first = base + __ffs(m) - 1;
        int pos = cnt + __popc(m & ((1u << lane) - 1u));
        if (hit && pos < KK) g[pos] = p;
        cnt += __popc(m);
        if (cnt >= KK) break;
    }
    if (cnt < KK) {
        for (int k = cnt + lane; k < KK; k += 32) g[k] = first;
    }
}

// ------------------------------------------------------------------
// Kernel 3: gather + 3-layer MLP + max-pool, FFMA2 over channel PAIRS.
// Per-channel accumulation order unchanged (bias init, ascending i)
// -> stays bit-exact vs the reference fp32 GEMM.
// Weight shared layout (interleaved pairs), float4 element f at
// (op, ip, c): c&1 selects channel 2op/2op+1, c>>1 selects input
// 2ip/2ip+1. One LDS.128 (ulonglong2) = 2 channel-pair fma2 steps.
//   sW1p [0, 4352)      (op<32, ip<34)
//   sW2p [4352, 12544)  (op<64, ip<32)
//   sW3p [12544, 45312) (op<128, ip<64)
//   sb1 [45312,45376) sb2 [45376,45504) sb3 [45504,45760)
// ------------------------------------------------------------------
#define OFF_W1 0
#define OFF_W2 4352
#define OFF_W3 12544
#define OFF_B1 45312
#define OFF_B2 45376
#define OFF_B3 45504
#define SMEM_FLOATS 45760

__global__ __launch_bounds__(256, 1)
void mlp_kernel(const float* __restrict__ xyz,
                const float* __restrict__ features,
                const float* __restrict__ W1, const float* __restrict__ b1,
                const float* __restrict__ W2, const float* __restrict__ b2,
                const float* __restrict__ W3, const float* __restrict__ b3,
                const float* __restrict__ newxyz,
                float* __restrict__ feats_out)
{
    extern __shared__ float sm[];
    const int tid  = threadIdx.x;
    const int lane = tid & 31;

    // ---- stage weights interleaved + biases ----
    for (int t = tid; t < 64 * 68; t += 256) {
        int f = t >> 2, c = t & 3;
        int op = f / 34, ip = f - op * 34;
        int ch = 2 * op + (c & 1);
        int i  = 2 * ip + (c >> 1);
        sm[OFF_W1 + t] = (i < 67) ? W1[ch * 67 + i] : 0.0f;
    }
    for (int t = tid; t < 128 * 64; t += 256) {
        int f = t >> 2, c = t & 3;
        int op = f >> 5, ip = f & 31;
        int ch = 2 * op + (c & 1);
        int i  = 2 * ip + (c >> 1);
        sm[OFF_W2 + t] = W2[ch * 64 + i];
    }
    for (int t = tid; t < 256 * 128; t += 256) {
        int f = t >> 2, c = t & 3;
        int op = f >> 6, ip = f & 63;
        int ch = 2 * op + (c & 1);
        int i  = 2 * ip + (c >> 1);
        sm[OFF_W3 + t] = W3[ch * 128 + i];
    }
    if (tid < 64)  sm[OFF_B1 + tid] = b1[tid];
    if (tid < 128) sm[OFF_B2 + tid] = b2[tid];
    sm[OFF_B3 + tid] = b3[tid & 255];
    __syncthreads();

    const int g = blockIdx.x * 8 + (tid >> 5);   // group id, 8192 total
    const int b = g >> 11;                       // g / 2048
    const int gi = g_grp[(size_t)g * KK + lane];

    // ---- h0 = [xyz - center (3), features (64), pad (1)] ----
    float h0[68];
    {
        const float* ctr  = newxyz + (size_t)g * 3;
        const float* pxyz = xyz + ((size_t)b * NN + gi) * 3;
        h0[0] = pxyz[0] - ctr[0];
        h0[1] = pxyz[1] - ctr[1];
        h0[2] = pxyz[2] - ctr[2];
        const float4* fr = (const float4*)(features + ((size_t)b * NN + gi) * DD);
#pragma unroll
        for (int t = 0; t < 16; t++) {
            float4 v = fr[t];
            h0[3 + 4 * t] = v.x; h0[4 + 4 * t] = v.y;
            h0[5 + 4 * t] = v.z; h0[6 + 4 * t] = v.w;
        }
        h0[67] = 0.0f;
    }

    const ulonglong2* w1p = (const ulonglong2*)(sm + OFF_W1);
    const ulonglong2* w2p = (const ulonglong2*)(sm + OFF_W2);
    const ulonglong2* w3p = (const ulonglong2*)(sm + OFF_W3);
    const unsigned long long* bb1 = (const unsigned long long*)(sm + OFF_B1);
    const unsigned long long* bb2 = (const unsigned long long*)(sm + OFF_B2);
    const unsigned long long* bb3 = (const unsigned long long*)(sm + OFF_B3);

    // ---- layer 1: 67(+pad) -> 64 : 32 channel-pair accumulators ----
    float h1[64];
    {
        unsigned long long acc[32];
#pragma unroll
        for (int op = 0; op < 32; op++) acc[op] = bb1[op];
#pragma unroll
        for (int ip = 0; ip < 34; ip++) {
            unsigned long long hd0 = pk2(h0[2 * ip],     h0[2 * ip]);
            unsigned long long hd1 = pk2(h0[2 * ip + 1], h0[2 * ip + 1]);
#pragma unroll
            for (int op = 0; op < 32; op++) {
                ulonglong2 w = w1p[op * 34 + ip];
                fma2(acc[op], w.x, hd0);
                fma2(acc[op], w.y, hd1);
            }
        }
#pragma unroll
        for (int op = 0; op < 32; op++) {
            float v0, v1; upk2(acc[op], v0, v1);
            h1[2 * op]     = fmaxf(v0, 0.0f);
            h1[2 * op + 1] = fmaxf(v1, 0.0f);
        }
    }

    // ---- layer 2: 64 -> 128 : two chunks of 32 pairs ----
    float h2[128];
#pragma unroll
    for (int oc = 0; oc < 2; oc++) {
        unsigned long long acc[32];
#pragma unroll
        for (int opl = 0; opl < 32; opl++) acc[opl] = bb2[oc * 32 + opl];
#pragma unroll
        for (int ip = 0; ip < 32; ip++) {
            unsigned long long hd0 = pk2(h1[2 * ip],     h1[2 * ip]);
            unsigned long long hd1 = pk2(h1[2 * ip + 1], h1[2 * ip + 1]);
#pragma unroll
            for (int opl = 0; opl < 32; opl++) {
                ulonglong2 w = w2p[(oc * 32 + opl) * 32 + ip];
                fma2(acc[opl], w.x, hd0);
                fma2(acc[opl], w.y, hd1);
            }
        }
#pragma unroll
        for (int opl = 0; opl < 32; opl++) {
            float v0, v1; upk2(acc[opl], v0, v1);
            h2[oc * 64 + 2 * opl]     = fmaxf(v0, 0.0f);
            h2[oc * 64 + 2 * opl + 1] = fmaxf(v1, 0.0f);
        }
    }

    // ---- layer 3: 128 -> 256 : 8 chunks of 16 pairs, fused max-pool ----
    float maxv[8];
#pragma unroll
    for (int cc = 0; cc < 8; cc++) {
        unsigned long long acc[16];
#pragma unroll
        for (int opl = 0; opl < 16; opl++) acc[opl] = bb3[cc * 16 + opl];
#pragma unroll
        for (int ip = 0; ip < 64; ip++) {
            unsigned long long hd0 = pk2(h2[2 * ip],     h2[2 * ip]);
            unsigned long long hd1 = pk2(h2[2 * ip + 1], h2[2 * ip + 1]);
#pragma unroll
            for (int opl = 0; opl < 16; opl++) {
                ulonglong2 w = w3p[(cc * 16 + opl) * 64 + ip];
                fma2(acc[opl], w.x, hd0);
                fma2(acc[opl], w.y, hd1);
            }
        }
        // relu + max over the 32 lanes (neighbors), lane j keeps channel j
#pragma unroll
        for (int opl = 0; opl < 16; opl++) {
            float v0, v1; upk2(acc[opl], v0, v1);
            v0 = fmaxf(v0, 0.0f);
            v1 = fmaxf(v1, 0.0f);
#pragma unroll
            for (int off = 16; off; off >>= 1) {
                v0 = fmaxf(v0, __shfl_xor_sync(0xffffffffu, v0, off));
                v1 = fmaxf(v1, __shfl_xor_sync(0xffffffffu, v1, off));
            }
            if (lane == 2 * opl)     maxv[cc] = v0;
            if (lane == 2 * opl + 1) maxv[cc] = v1;
        }
    }
#pragma unroll
    for (int cc = 0; cc < 8; cc++)
        feats_out[(size_t)g * 256 + cc * 32 + lane] = maxv[cc];
}

// ------------------------------------------------------------------
extern "C" void kernel_launch(void* const* d_in, const int* in_sizes, int n_in,
                              void* d_out, int out_size)
{
    const float* xyz      = (const float*)d_in[0];
    const float* features = (const float*)d_in[1];
    const float* W1 = (const float*)d_in[2];
    const float* b1 = (const float*)d_in[3];
    const float* W2 = (const float*)d_in[4];
    const float* b2 = (const float*)d_in[5];
    const float* W3 = (const float*)d_in[6];
    const float* b3 = (const float*)d_in[7];

    float* out    = (float*)d_out;
    float* newxyz = out;                         // [B,S,3] = 24576 floats
    float* feats  = out + (size_t)BB * SS * 3;   // [B,S,256]

    cudaFuncSetAttribute(fps_kernel, cudaFuncAttributeMaxDynamicSharedMemorySize,
                         NN * (int)sizeof(float4));
    cudaFuncSetAttribute(mlp_kernel, cudaFuncAttributeMaxDynamicSharedMemorySize,
                         SMEM_FLOATS * (int)sizeof(float));

    fps_kernel<<<BB, 1024, NN * sizeof(float4)>>>(xyz, newxyz);
    ballq_kernel<<<(BB * SS * 32) / 256, 256>>>(xyz, newxyz);
    mlp_kernel<<<(BB * SS) / 8, 256, SMEM_FLOATS * sizeof(float)>>>(
        xyz, features, W1, b1, W2, b2, W3, b3, newxyz, feats);
}